// round 2
// baseline (speedup 1.0000x reference)
#include <cuda_runtime.h>

#define FLTMAX 3.402823466e+38f

// ---------------- device scratch (no allocations allowed) ----------------
__device__ float g_y1[32768 * 32];      // conv1 output [B*N, 32]
__device__ float g_feats[32768 * 64];   // conv2 output [B*N, 64]
__device__ float g_stats[192];          // [0:32) sum1, [32:64) sq1, [64:128) sum2, [128:192) sq2
__device__ float g_bn1[64];             // scale[32], shift[32]
__device__ float g_bn2[128];            // scale[64], shift[64]
__device__ int   g_fps[16384];          // [B, 2048]
__device__ float g_pooled[16384 * 67];  // [B*S, 67]
__device__ float g_y3[16384 * 64];      // conv3 output [B*S, 64]

// ---------------- zero the stat accumulators ----------------
__global__ void zero_stats_kernel() {
    int t = threadIdx.x;
    if (t < 192) g_stats[t] = 0.0f;
}

// ---------------- conv1 (3->32) + BN1 stats ----------------
__global__ void mlp1_kernel(const float* __restrict__ x, const float* __restrict__ W1,
                            const float* __restrict__ b1) {
    __shared__ float sW[96], sb[32], ssum[32], ssq[32];
    int tid = threadIdx.x;
    if (tid < 96) sW[tid] = W1[tid];
    if (tid < 32) { sb[tid] = b1[tid]; ssum[tid] = 0.0f; ssq[tid] = 0.0f; }
    __syncthreads();
    int p = blockIdx.x * 256 + tid;
    float X = x[3 * p], Y = x[3 * p + 1], Z = x[3 * p + 2];
    int lane = tid & 31;
    for (int c = 0; c < 32; c++) {
        float v = fmaf(sW[3 * c + 2], Z, fmaf(sW[3 * c + 1], Y, fmaf(sW[3 * c], X, sb[c])));
        g_y1[p * 32 + c] = v;
        float s = v, q = v * v;
        #pragma unroll
        for (int off = 16; off; off >>= 1) {
            s += __shfl_down_sync(0xffffffffu, s, off);
            q += __shfl_down_sync(0xffffffffu, q, off);
        }
        if (lane == 0) { atomicAdd(&ssum[c], s); atomicAdd(&ssq[c], q); }
    }
    __syncthreads();
    if (tid < 32) {
        atomicAdd(&g_stats[tid], ssum[tid]);
        atomicAdd(&g_stats[32 + tid], ssq[tid]);
    }
}

// ---------------- finalize BN1 ----------------
__global__ void bnfin1_kernel(const float* __restrict__ g1, const float* __restrict__ be1) {
    int c = threadIdx.x;
    if (c >= 32) return;
    const float n = 32768.0f;
    float mean = g_stats[c] / n;
    float var  = g_stats[32 + c] / n - mean * mean;
    float sc   = g1[c] * rsqrtf(var + 1e-5f);
    g_bn1[c] = sc;
    g_bn1[32 + c] = be1[c] - mean * sc;
}

// ---------------- BN1+ReLU+conv2 (32->64) ----------------
__global__ void mlp2_kernel(const float* __restrict__ W2, const float* __restrict__ b2) {
    __shared__ float sW[2048], sb[64], sc[32], sh[32];
    int tid = threadIdx.x;
    for (int i = tid; i < 2048; i += 256) sW[i] = W2[i];
    if (tid < 64) sb[tid] = b2[tid];
    if (tid < 32) { sc[tid] = g_bn1[tid]; sh[tid] = g_bn1[32 + tid]; }
    __syncthreads();
    int p = blockIdx.x * 256 + tid;
    float t[32];
    #pragma unroll
    for (int c = 0; c < 32; c++)
        t[c] = fmaxf(fmaf(g_y1[p * 32 + c], sc[c], sh[c]), 0.0f);
    for (int o = 0; o < 64; o++) {
        float acc = sb[o];
        #pragma unroll
        for (int c = 0; c < 32; c++) acc = fmaf(sW[o * 32 + c], t[c], acc);
        g_feats[p * 64 + o] = acc;
    }
}

// ---------------- farthest point sampling: 1 CTA per batch ----------------
// Bit-exact with reference: d = ((dx*dx + dy*dy) + dz*dz), dist = min(dist, d),
// argmax = first occurrence of max (lowest index on tie).
__global__ void fps_kernel(const float* __restrict__ x) {
    extern __shared__ float sm[];
    float* px = sm;
    float* py = sm + 4096;
    float* pz = sm + 8192;
    __shared__ float rv[8];
    __shared__ int   ri[8];
    __shared__ int   sfar;
    int b = blockIdx.x, tid = threadIdx.x;
    const float* xb = x + b * 12288;

    float lx[16], ly[16], lz[16], dd[16];
    #pragma unroll
    for (int k = 0; k < 16; k++) {
        int i = tid + k * 256;
        float X = xb[3 * i], Y = xb[3 * i + 1], Z = xb[3 * i + 2];
        px[i] = X; py[i] = Y; pz[i] = Z;
        lx[k] = X; ly[k] = Y; lz[k] = Z;
        dd[k] = FLTMAX;
    }
    __syncthreads();

    int far = 0;
    int lane = tid & 31, warp = tid >> 5;
    int* outp = g_fps + b * 2048;

    for (int s = 0; s < 2048; s++) {
        if (tid == 0) outp[s] = far;
        float cx = px[far], cy = py[far], cz = pz[far];
        float bv = -1.0f;
        int   bi = 0x7fffffff;
        #pragma unroll
        for (int k = 0; k < 16; k++) {
            float dx = __fsub_rn(lx[k], cx);
            float dy = __fsub_rn(ly[k], cy);
            float dz = __fsub_rn(lz[k], cz);
            float d  = __fadd_rn(__fadd_rn(__fmul_rn(dx, dx), __fmul_rn(dy, dy)),
                                 __fmul_rn(dz, dz));
            float nd = fminf(dd[k], d);
            dd[k] = nd;
            if (nd > bv) { bv = nd; bi = tid + k * 256; }
        }
        #pragma unroll
        for (int off = 16; off; off >>= 1) {
            float ov = __shfl_down_sync(0xffffffffu, bv, off);
            int   oi = __shfl_down_sync(0xffffffffu, bi, off);
            if (ov > bv || (ov == bv && oi < bi)) { bv = ov; bi = oi; }
        }
        if (lane == 0) { rv[warp] = bv; ri[warp] = bi; }
        __syncthreads();
        if (warp == 0) {
            float v  = (lane < 8) ? rv[lane] : -1.0f;
            int   i2 = (lane < 8) ? ri[lane] : 0x7fffffff;
            #pragma unroll
            for (int off = 4; off; off >>= 1) {
                float ov = __shfl_down_sync(0xffffffffu, v, off);
                int   oi = __shfl_down_sync(0xffffffffu, i2, off);
                if (ov > v || (ov == v && oi < i2)) { v = ov; i2 = oi; }
            }
            if (lane == 0) sfar = i2;
        }
        __syncthreads();
        far = sfar;
    }
}

// ---------------- 16-NN + group + maxpool, fused ----------------
// d = (|q|^2 + |p|^2) - 2*(q.p); keep 16 smallest, ties keep lowest index.
__global__ void __launch_bounds__(128) knn_pool_kernel(const float* __restrict__ x) {
    __shared__ float tx[1024], ty[1024], tz[1024], tn[1024];
    int b = blockIdx.y;
    int s = blockIdx.x * 128 + threadIdx.x;
    const float* xb = x + b * 12288;
    int qi = g_fps[b * 2048 + s];
    float qx = xb[3 * qi], qy = xb[3 * qi + 1], qz = xb[3 * qi + 2];
    float qn = __fadd_rn(__fadd_rn(__fmul_rn(qx, qx), __fmul_rn(qy, qy)), __fmul_rn(qz, qz));

    float bd[16];
    int   bi[16];
    #pragma unroll
    for (int m = 0; m < 16; m++) { bd[m] = FLTMAX; bi[m] = 0x7fffffff; }
    float w = FLTMAX;
    int ws = 0;

    for (int t = 0; t < 4; t++) {
        __syncthreads();
        for (int j = threadIdx.x; j < 1024; j += 128) {
            int i = t * 1024 + j;
            float X = xb[3 * i], Y = xb[3 * i + 1], Z = xb[3 * i + 2];
            tx[j] = X; ty[j] = Y; tz[j] = Z;
            tn[j] = __fadd_rn(__fadd_rn(__fmul_rn(X, X), __fmul_rn(Y, Y)), __fmul_rn(Z, Z));
        }
        __syncthreads();
        for (int j = 0; j < 1024; j++) {
            float dot = __fadd_rn(__fadd_rn(__fmul_rn(qx, tx[j]), __fmul_rn(qy, ty[j])),
                                  __fmul_rn(qz, tz[j]));
            float d = __fsub_rn(__fadd_rn(qn, tn[j]), __fmul_rn(2.0f, dot));
            if (d < w) {
                int i = t * 1024 + j;
                #pragma unroll
                for (int m = 0; m < 16; m++)
                    if (m == ws) { bd[m] = d; bi[m] = i; }
                // rescan: worst = max dist, tie -> larger index (evicted first)
                float nw = -FLTMAX; int nwi = -1; int nws = 0;
                #pragma unroll
                for (int m = 0; m < 16; m++) {
                    bool better = (bd[m] > nw) || (bd[m] == nw && bi[m] > nwi);
                    if (better) { nw = bd[m]; nwi = bi[m]; nws = m; }
                }
                w = nw; ws = nws;
            }
        }
    }

    // fused group + maxpool
    float mx = -FLTMAX, my = -FLTMAX, mz = -FLTMAX;
    float4 acc[16];
    #pragma unroll
    for (int q = 0; q < 16; q++) acc[q] = make_float4(-FLTMAX, -FLTMAX, -FLTMAX, -FLTMAX);
    const float* fb = g_feats + b * 4096 * 64;
    #pragma unroll
    for (int k = 0; k < 16; k++) {
        int i = bi[k];
        mx = fmaxf(mx, __fsub_rn(xb[3 * i], qx));
        my = fmaxf(my, __fsub_rn(xb[3 * i + 1], qy));
        mz = fmaxf(mz, __fsub_rn(xb[3 * i + 2], qz));
        const float4* fr = (const float4*)(fb + i * 64);
        #pragma unroll
        for (int q = 0; q < 16; q++) {
            float4 f = fr[q];
            acc[q].x = fmaxf(acc[q].x, f.x);
            acc[q].y = fmaxf(acc[q].y, f.y);
            acc[q].z = fmaxf(acc[q].z, f.z);
            acc[q].w = fmaxf(acc[q].w, f.w);
        }
    }
    float* op = g_pooled + (b * 2048 + s) * 67;
    op[0] = mx; op[1] = my; op[2] = mz;
    #pragma unroll
    for (int q = 0; q < 16; q++) {
        op[3 + 4 * q] = acc[q].x;
        op[4 + 4 * q] = acc[q].y;
        op[5 + 4 * q] = acc[q].z;
        op[6 + 4 * q] = acc[q].w;
    }
}

// ---------------- conv3 (67->64) + BN2 stats ----------------
__global__ void mlp3_kernel(const float* __restrict__ W3, const float* __restrict__ b3) {
    __shared__ float sW[64 * 67];
    __shared__ float sb[64], ssum[64], ssq[64];
    int tid = threadIdx.x;
    for (int i = tid; i < 4288; i += 256) sW[i] = W3[i];
    if (tid < 64) { sb[tid] = b3[tid]; ssum[tid] = 0.0f; ssq[tid] = 0.0f; }
    __syncthreads();
    int p = blockIdx.x * 256 + tid;
    float t[67];
    #pragma unroll
    for (int c = 0; c < 67; c++) t[c] = g_pooled[p * 67 + c];
    int lane = tid & 31;
    for (int o = 0; o < 64; o++) {
        float acc = sb[o];
        #pragma unroll
        for (int c = 0; c < 67; c++) acc = fmaf(sW[o * 67 + c], t[c], acc);
        g_y3[p * 64 + o] = acc;
        float sv = acc, sq = acc * acc;
        #pragma unroll
        for (int off = 16; off; off >>= 1) {
            sv += __shfl_down_sync(0xffffffffu, sv, off);
            sq += __shfl_down_sync(0xffffffffu, sq, off);
        }
        if (lane == 0) { atomicAdd(&ssum[o], sv); atomicAdd(&ssq[o], sq); }
    }
    __syncthreads();
    if (tid < 64) {
        atomicAdd(&g_stats[64 + tid], ssum[tid]);
        atomicAdd(&g_stats[128 + tid], ssq[tid]);
    }
}

// ---------------- finalize BN2 ----------------
__global__ void bnfin2_kernel(const float* __restrict__ g2, const float* __restrict__ be2) {
    int c = threadIdx.x;
    if (c >= 64) return;
    const float n = 16384.0f;
    float mean = g_stats[64 + c] / n;
    float var  = g_stats[128 + c] / n - mean * mean;
    float sc   = g2[c] * rsqrtf(var + 1e-5f);
    g_bn2[c] = sc;
    g_bn2[64 + c] = be2[c] - mean * sc;
}

// ---------------- BN2+ReLU+conv4 (64->64) -> output ----------------
__global__ void mlp4_kernel(const float* __restrict__ W4, const float* __restrict__ b4,
                            float* __restrict__ out) {
    __shared__ float sW[4096], sb[64], sc[64], sh[64];
    int tid = threadIdx.x;
    for (int i = tid; i < 4096; i += 256) sW[i] = W4[i];
    if (tid < 64) { sb[tid] = b4[tid]; sc[tid] = g_bn2[tid]; sh[tid] = g_bn2[64 + tid]; }
    __syncthreads();
    int p = blockIdx.x * 256 + tid;
    float t[64];
    #pragma unroll
    for (int c = 0; c < 64; c++)
        t[c] = fmaxf(fmaf(g_y3[p * 64 + c], sc[c], sh[c]), 0.0f);
    for (int o = 0; o < 64; o++) {
        float acc = sb[o];
        #pragma unroll
        for (int c = 0; c < 64; c++) acc = fmaf(sW[o * 64 + c], t[c], acc);
        out[p * 64 + o] = acc;
    }
}

// ---------------- launch ----------------
extern "C" void kernel_launch(void* const* d_in, const int* in_sizes, int n_in,
                              void* d_out, int out_size) {
    const float* x   = (const float*)d_in[0];
    const float* W1  = (const float*)d_in[1];
    const float* b1  = (const float*)d_in[2];
    const float* g1  = (const float*)d_in[3];
    const float* be1 = (const float*)d_in[4];
    const float* W2  = (const float*)d_in[5];
    const float* b2  = (const float*)d_in[6];
    const float* W3  = (const float*)d_in[7];
    const float* b3  = (const float*)d_in[8];
    const float* g2  = (const float*)d_in[9];
    const float* be2 = (const float*)d_in[10];
    const float* W4  = (const float*)d_in[11];
    const float* b4  = (const float*)d_in[12];
    float* out = (float*)d_out;

    cudaFuncSetAttribute(fps_kernel, cudaFuncAttributeMaxDynamicSharedMemorySize, 50000);

    zero_stats_kernel<<<1, 192>>>();
    fps_kernel<<<8, 256, 49152>>>(x);
    mlp1_kernel<<<128, 256>>>(x, W1, b1);
    bnfin1_kernel<<<1, 32>>>(g1, be1);
    mlp2_kernel<<<128, 256>>>(W2, b2);
    knn_pool_kernel<<<dim3(16, 8), 128>>>(x);
    mlp3_kernel<<<64, 256>>>(W3, b3);
    bnfin2_kernel<<<1, 64>>>(g2, be2);
    mlp4_kernel<<<64, 256>>>(W4, b4, out);
}

// round 3
// speedup vs baseline: 1.2949x; 1.2949x over previous
#include <cuda_runtime.h>

#define FLTMAX 3.402823466e+38f

// ---------------- device scratch ----------------
__device__ float g_y1[32768 * 32];      // conv1 output [B*N, 32]
__device__ float g_feats[32768 * 64];   // conv2 output [B*N, 64]
__device__ float g_p1[32 * 64];         // mlp1 per-block partials [32 blk][sum32|sq32]
__device__ float g_p2[64 * 128];        // mlp3 per-block partials [64 blk][sum64|sq64]
__device__ float g_bn1[64];             // scale[32], shift[32]
__device__ float g_bn2[128];            // scale[64], shift[64]
__device__ int   g_fps[16384];          // [B, 2048]
__device__ float g_pooled[16384 * 67];  // [B*S, 67]
__device__ float g_y3[16384 * 64];      // conv3 output [B*S, 64]

// ---------------- packed f32x2 helpers (per-lane .rn == scalar .rn) ----------------
__device__ __forceinline__ unsigned long long f2_add(unsigned long long a, unsigned long long b) {
    unsigned long long r;
    asm("add.rn.f32x2 %0, %1, %2;" : "=l"(r) : "l"(a), "l"(b));
    return r;
}
__device__ __forceinline__ unsigned long long f2_mul(unsigned long long a, unsigned long long b) {
    unsigned long long r;
    asm("mul.rn.f32x2 %0, %1, %2;" : "=l"(r) : "l"(a), "l"(b));
    return r;
}
__device__ __forceinline__ unsigned long long f2_pack(float lo, float hi) {
    unsigned long long r;
    asm("mov.b64 %0, {%1, %2};" : "=l"(r) : "f"(lo), "f"(hi));
    return r;
}
__device__ __forceinline__ float2 f2_unpack(unsigned long long v) {
    float2 f;
    asm("mov.b64 {%0, %1}, %2;" : "=f"(f.x), "=f"(f.y) : "l"(v));
    return f;
}

// ---------------- fused FPS (blocks 0-7) + mlp1 (blocks 8-39) ----------------
__global__ void __launch_bounds__(1024, 1)
fps_mlp1_kernel(const float* __restrict__ x, const float* __restrict__ W1,
                const float* __restrict__ b1) {
    if (blockIdx.x < 8) {
        // ======== FPS: one CTA per batch, 1024 threads, 4 pts/thread (2 packed pairs)
        extern __shared__ float sm[];
        float* px = sm;
        float* py = sm + 4096;
        float* pz = sm + 8192;
        __shared__ unsigned rv[32];
        __shared__ unsigned ri[32];
        __shared__ int sfar;
        int b = blockIdx.x, tid = threadIdx.x;
        int lane = tid & 31, warp = tid >> 5;
        const float* xb = x + b * 12288;

        // pair A: points 2t, 2t+1 ; pair B: points 2t+2048, 2t+2049
        int iA = 2 * tid, iB = 2 * tid + 2048;
        float ax0 = xb[3 * iA],     ay0 = xb[3 * iA + 1], az0 = xb[3 * iA + 2];
        float ax1 = xb[3 * iA + 3], ay1 = xb[3 * iA + 4], az1 = xb[3 * iA + 5];
        float bx0 = xb[3 * iB],     by0 = xb[3 * iB + 1], bz0 = xb[3 * iB + 2];
        float bx1 = xb[3 * iB + 3], by1 = xb[3 * iB + 4], bz1 = xb[3 * iB + 5];
        px[iA] = ax0; py[iA] = ay0; pz[iA] = az0;
        px[iA + 1] = ax1; py[iA + 1] = ay1; pz[iA + 1] = az1;
        px[iB] = bx0; py[iB] = by0; pz[iB] = bz0;
        px[iB + 1] = bx1; py[iB + 1] = by1; pz[iB + 1] = bz1;
        unsigned long long pxa = f2_pack(ax0, ax1), pya = f2_pack(ay0, ay1), pza = f2_pack(az0, az1);
        unsigned long long pxb = f2_pack(bx0, bx1), pyb = f2_pack(by0, by1), pzb = f2_pack(bz0, bz1);
        float dd0 = FLTMAX, dd1 = FLTMAX, dd2 = FLTMAX, dd3 = FLTMAX;
        __syncthreads();

        int far = 0;
        int* outp = g_fps + b * 2048;

        for (int s = 0; s < 2048; s++) {
            if (tid == 0) outp[s] = far;
            float cx = px[far], cy = py[far], cz = pz[far];
            unsigned long long ncx = f2_pack(-cx, -cx);
            unsigned long long ncy = f2_pack(-cy, -cy);
            unsigned long long ncz = f2_pack(-cz, -cz);

            // pair A: d = (dx*dx + dy*dy) + dz*dz, each op RN (== __fsub/__fmul/__fadd_rn)
            unsigned long long dxa = f2_add(pxa, ncx);
            unsigned long long dya = f2_add(pya, ncy);
            unsigned long long dza = f2_add(pza, ncz);
            unsigned long long da = f2_add(f2_add(f2_mul(dxa, dxa), f2_mul(dya, dya)),
                                           f2_mul(dza, dza));
            unsigned long long dxb = f2_add(pxb, ncx);
            unsigned long long dyb = f2_add(pyb, ncy);
            unsigned long long dzb = f2_add(pzb, ncz);
            unsigned long long db = f2_add(f2_add(f2_mul(dxb, dxb), f2_mul(dyb, dyb)),
                                           f2_mul(dzb, dzb));
            float2 fa = f2_unpack(da);
            float2 fb = f2_unpack(db);
            dd0 = fminf(dd0, fa.x);
            dd1 = fminf(dd1, fa.y);
            dd2 = fminf(dd2, fb.x);
            dd3 = fminf(dd3, fb.y);

            // local argmax, ascending global index order -> strict > keeps lowest idx
            float bv = dd0; int bi = iA;
            if (dd1 > bv) { bv = dd1; bi = iA + 1; }
            if (dd2 > bv) { bv = dd2; bi = iB; }
            if (dd3 > bv) { bv = dd3; bi = iB + 1; }

            // warp argmax via redux (dists >= 0 -> float bits monotone as u32)
            unsigned vb = __float_as_uint(bv);
            unsigned wm = __reduce_max_sync(0xffffffffu, vb);
            unsigned cand = (vb == wm) ? (unsigned)bi : 0xffffffffu;
            unsigned wi = __reduce_min_sync(0xffffffffu, cand);
            if (lane == 0) { rv[warp] = wm; ri[warp] = wi; }
            __syncthreads();
            if (warp == 0) {
                unsigned v = rv[lane];
                unsigned i2 = ri[lane];
                unsigned m2 = __reduce_max_sync(0xffffffffu, v);
                unsigned c2 = (v == m2) ? i2 : 0xffffffffu;
                unsigned g = __reduce_min_sync(0xffffffffu, c2);
                if (lane == 0) sfar = (int)g;
            }
            __syncthreads();
            far = sfar;
        }
    } else {
        // ======== mlp1: conv1 (3->32) + BN1 partial stats, 1 point/thread
        __shared__ float sW[96], sb[32], ssum[32], ssq[32];
        int tid = threadIdx.x;
        int blk = blockIdx.x - 8;
        if (tid < 96) sW[tid] = W1[tid];
        if (tid < 32) { sb[tid] = b1[tid]; ssum[tid] = 0.0f; ssq[tid] = 0.0f; }
        __syncthreads();
        int p = blk * 1024 + tid;
        float X = x[3 * p], Y = x[3 * p + 1], Z = x[3 * p + 2];
        int lane = tid & 31;
        for (int c = 0; c < 32; c++) {
            float v = fmaf(sW[3 * c + 2], Z, fmaf(sW[3 * c + 1], Y, fmaf(sW[3 * c], X, sb[c])));
            g_y1[p * 32 + c] = v;
            float s = v, q = v * v;
            #pragma unroll
            for (int off = 16; off; off >>= 1) {
                s += __shfl_down_sync(0xffffffffu, s, off);
                q += __shfl_down_sync(0xffffffffu, q, off);
            }
            if (lane == 0) { atomicAdd(&ssum[c], s); atomicAdd(&ssq[c], q); }
        }
        __syncthreads();
        if (tid < 32) {
            g_p1[blk * 64 + tid] = ssum[tid];
            g_p1[blk * 64 + 32 + tid] = ssq[tid];
        }
    }
}

// ---------------- finalize BN1 (reduce 32 partials) ----------------
__global__ void bnfin1_kernel(const float* __restrict__ g1, const float* __restrict__ be1) {
    int c = threadIdx.x;
    if (c >= 32) return;
    float sum = 0.0f, sq = 0.0f;
    for (int b = 0; b < 32; b++) {
        sum += g_p1[b * 64 + c];
        sq  += g_p1[b * 64 + 32 + c];
    }
    const float n = 32768.0f;
    float mean = sum / n;
    float var  = sq / n - mean * mean;
    float sc   = g1[c] * rsqrtf(var + 1e-5f);
    g_bn1[c] = sc;
    g_bn1[32 + c] = be1[c] - mean * sc;
}

// ---------------- BN1+ReLU+conv2 (32->64) ----------------
__global__ void mlp2_kernel(const float* __restrict__ W2, const float* __restrict__ b2) {
    __shared__ float sW[2048], sb[64], sc[32], sh[32];
    int tid = threadIdx.x;
    for (int i = tid; i < 2048; i += 256) sW[i] = W2[i];
    if (tid < 64) sb[tid] = b2[tid];
    if (tid < 32) { sc[tid] = g_bn1[tid]; sh[tid] = g_bn1[32 + tid]; }
    __syncthreads();
    int p = blockIdx.x * 256 + tid;
    float t[32];
    #pragma unroll
    for (int c = 0; c < 32; c++)
        t[c] = fmaxf(fmaf(g_y1[p * 32 + c], sc[c], sh[c]), 0.0f);
    for (int o = 0; o < 64; o++) {
        float acc = sb[o];
        #pragma unroll
        for (int c = 0; c < 32; c++) acc = fmaf(sW[o * 32 + c], t[c], acc);
        g_feats[p * 64 + o] = acc;
    }
}

// ---------------- 16-NN + group + maxpool, fused (packed f32x2 scan) ----------------
__global__ void __launch_bounds__(128) knn_pool_kernel(const float* __restrict__ x) {
    __shared__ float2 tx2[512], ty2[512], tz2[512], tn2[512];
    float* tx = (float*)tx2; float* ty = (float*)ty2;
    float* tz = (float*)tz2; float* tn = (float*)tn2;
    int b = blockIdx.y;
    int s = blockIdx.x * 128 + threadIdx.x;
    const float* xb = x + b * 12288;
    int qi = g_fps[b * 2048 + s];
    float qx = xb[3 * qi], qy = xb[3 * qi + 1], qz = xb[3 * qi + 2];
    float qn = __fadd_rn(__fadd_rn(__fmul_rn(qx, qx), __fmul_rn(qy, qy)), __fmul_rn(qz, qz));
    unsigned long long qx2 = f2_pack(qx, qx), qy2 = f2_pack(qy, qy), qz2 = f2_pack(qz, qz);
    unsigned long long qn2 = f2_pack(qn, qn), n2 = f2_pack(-2.0f, -2.0f);

    float bd[16];
    int   bi[16];
    #pragma unroll
    for (int m = 0; m < 16; m++) { bd[m] = FLTMAX; bi[m] = 0x7fffffff; }
    float w = FLTMAX;
    int ws = 0;

    for (int t = 0; t < 4; t++) {
        __syncthreads();
        for (int j = threadIdx.x; j < 1024; j += 128) {
            int i = t * 1024 + j;
            float X = xb[3 * i], Y = xb[3 * i + 1], Z = xb[3 * i + 2];
            tx[j] = X; ty[j] = Y; tz[j] = Z;
            tn[j] = __fadd_rn(__fadd_rn(__fmul_rn(X, X), __fmul_rn(Y, Y)), __fmul_rn(Z, Z));
        }
        __syncthreads();
        for (int j = 0; j < 1024; j += 2) {
            float2 vx = tx2[j >> 1], vy = ty2[j >> 1], vz = tz2[j >> 1], vn = tn2[j >> 1];
            unsigned long long txp = f2_pack(vx.x, vx.y);
            unsigned long long typ = f2_pack(vy.x, vy.y);
            unsigned long long tzp = f2_pack(vz.x, vz.y);
            unsigned long long tnp = f2_pack(vn.x, vn.y);
            // dot = (qx*tx + qy*ty) + qz*tz ; d = (qn + tn) + dot*(-2)  [== (qn+tn)-2*dot]
            unsigned long long dot = f2_add(f2_add(f2_mul(qx2, txp), f2_mul(qy2, typ)),
                                            f2_mul(qz2, tzp));
            unsigned long long d2 = f2_add(f2_add(qn2, tnp), f2_mul(dot, n2));
            float2 d = f2_unpack(d2);
            #pragma unroll
            for (int h = 0; h < 2; h++) {
                float dv = h ? d.y : d.x;
                if (dv < w) {
                    int i = t * 1024 + j + h;
                    #pragma unroll
                    for (int m = 0; m < 16; m++)
                        if (m == ws) { bd[m] = dv; bi[m] = i; }
                    float nw = -FLTMAX; int nwi = -1; int nws = 0;
                    #pragma unroll
                    for (int m = 0; m < 16; m++) {
                        bool better = (bd[m] > nw) || (bd[m] == nw && bi[m] > nwi);
                        if (better) { nw = bd[m]; nwi = bi[m]; nws = m; }
                    }
                    w = nw; ws = nws;
                }
            }
        }
    }

    // fused group + maxpool
    float mx = -FLTMAX, my = -FLTMAX, mz = -FLTMAX;
    float4 acc[16];
    #pragma unroll
    for (int q = 0; q < 16; q++) acc[q] = make_float4(-FLTMAX, -FLTMAX, -FLTMAX, -FLTMAX);
    const float* fb = g_feats + b * 4096 * 64;
    #pragma unroll
    for (int k = 0; k < 16; k++) {
        int i = bi[k];
        mx = fmaxf(mx, __fsub_rn(xb[3 * i], qx));
        my = fmaxf(my, __fsub_rn(xb[3 * i + 1], qy));
        mz = fmaxf(mz, __fsub_rn(xb[3 * i + 2], qz));
        const float4* fr = (const float4*)(fb + i * 64);
        #pragma unroll
        for (int q = 0; q < 16; q++) {
            float4 f = fr[q];
            acc[q].x = fmaxf(acc[q].x, f.x);
            acc[q].y = fmaxf(acc[q].y, f.y);
            acc[q].z = fmaxf(acc[q].z, f.z);
            acc[q].w = fmaxf(acc[q].w, f.w);
        }
    }
    float* op = g_pooled + (b * 2048 + s) * 67;
    op[0] = mx; op[1] = my; op[2] = mz;
    #pragma unroll
    for (int q = 0; q < 16; q++) {
        op[3 + 4 * q] = acc[q].x;
        op[4 + 4 * q] = acc[q].y;
        op[5 + 4 * q] = acc[q].z;
        op[6 + 4 * q] = acc[q].w;
    }
}

// ---------------- conv3 (67->64) + BN2 partial stats ----------------
__global__ void mlp3_kernel(const float* __restrict__ W3, const float* __restrict__ b3) {
    __shared__ float sW[64 * 67];
    __shared__ float sb[64], ssum[64], ssq[64];
    int tid = threadIdx.x;
    for (int i = tid; i < 4288; i += 256) sW[i] = W3[i];
    if (tid < 64) { sb[tid] = b3[tid]; ssum[tid] = 0.0f; ssq[tid] = 0.0f; }
    __syncthreads();
    int p = blockIdx.x * 256 + tid;
    float t[67];
    #pragma unroll
    for (int c = 0; c < 67; c++) t[c] = g_pooled[p * 67 + c];
    int lane = tid & 31;
    for (int o = 0; o < 64; o++) {
        float acc = sb[o];
        #pragma unroll
        for (int c = 0; c < 67; c++) acc = fmaf(sW[o * 67 + c], t[c], acc);
        g_y3[p * 64 + o] = acc;
        float sv = acc, sq = acc * acc;
        #pragma unroll
        for (int off = 16; off; off >>= 1) {
            sv += __shfl_down_sync(0xffffffffu, sv, off);
            sq += __shfl_down_sync(0xffffffffu, sq, off);
        }
        if (lane == 0) { atomicAdd(&ssum[o], sv); atomicAdd(&ssq[o], sq); }
    }
    __syncthreads();
    if (tid < 64) {
        g_p2[blockIdx.x * 128 + tid] = ssum[tid];
        g_p2[blockIdx.x * 128 + 64 + tid] = ssq[tid];
    }
}

// ---------------- finalize BN2 (reduce 64 partials) ----------------
__global__ void bnfin2_kernel(const float* __restrict__ g2, const float* __restrict__ be2) {
    int c = threadIdx.x;
    if (c >= 64) return;
    float sum = 0.0f, sq = 0.0f;
    for (int b = 0; b < 64; b++) {
        sum += g_p2[b * 128 + c];
        sq  += g_p2[b * 128 + 64 + c];
    }
    const float n = 16384.0f;
    float mean = sum / n;
    float var  = sq / n - mean * mean;
    float sc   = g2[c] * rsqrtf(var + 1e-5f);
    g_bn2[c] = sc;
    g_bn2[64 + c] = be2[c] - mean * sc;
}

// ---------------- BN2+ReLU+conv4 (64->64) -> output ----------------
__global__ void mlp4_kernel(const float* __restrict__ W4, const float* __restrict__ b4,
                            float* __restrict__ out) {
    __shared__ float sW[4096], sb[64], sc[64], sh[64];
    int tid = threadIdx.x;
    for (int i = tid; i < 4096; i += 256) sW[i] = W4[i];
    if (tid < 64) { sb[tid] = b4[tid]; sc[tid] = g_bn2[tid]; sh[tid] = g_bn2[64 + tid]; }
    __syncthreads();
    int p = blockIdx.x * 256 + tid;
    float t[64];
    #pragma unroll
    for (int c = 0; c < 64; c++)
        t[c] = fmaxf(fmaf(g_y3[p * 64 + c], sc[c], sh[c]), 0.0f);
    for (int o = 0; o < 64; o++) {
        float acc = sb[o];
        #pragma unroll
        for (int c = 0; c < 64; c++) acc = fmaf(sW[o * 64 + c], t[c], acc);
        out[p * 64 + o] = acc;
    }
}

// ---------------- launch ----------------
extern "C" void kernel_launch(void* const* d_in, const int* in_sizes, int n_in,
                              void* d_out, int out_size) {
    const float* x   = (const float*)d_in[0];
    const float* W1  = (const float*)d_in[1];
    const float* b1  = (const float*)d_in[2];
    const float* g1  = (const float*)d_in[3];
    const float* be1 = (const float*)d_in[4];
    const float* W2  = (const float*)d_in[5];
    const float* b2  = (const float*)d_in[6];
    const float* W3  = (const float*)d_in[7];
    const float* b3  = (const float*)d_in[8];
    const float* g2  = (const float*)d_in[9];
    const float* be2 = (const float*)d_in[10];
    const float* W4  = (const float*)d_in[11];
    const float* b4  = (const float*)d_in[12];
    float* out = (float*)d_out;

    cudaFuncSetAttribute(fps_mlp1_kernel, cudaFuncAttributeMaxDynamicSharedMemorySize, 50000);

    fps_mlp1_kernel<<<40, 1024, 49152>>>(x, W1, b1);   // FPS (8 CTAs) || mlp1 (32 CTAs)
    bnfin1_kernel<<<1, 32>>>(g1, be1);
    mlp2_kernel<<<128, 256>>>(W2, b2);
    knn_pool_kernel<<<dim3(16, 8), 128>>>(x);
    mlp3_kernel<<<64, 256>>>(W3, b3);
    bnfin2_kernel<<<1, 64>>>(g2, be2);
    mlp4_kernel<<<64, 256>>>(W4, b4, out);
}

// round 4
// speedup vs baseline: 1.5088x; 1.1652x over previous
#include <cuda_runtime.h>

#define FLTMAX 3.402823466e+38f

// ---------------- device scratch ----------------
__device__ float g_y1[32768 * 32];      // conv1 output [B*N, 32]
__device__ float g_feats[32768 * 64];   // conv2 output [B*N, 64]
__device__ float g_p1[64 * 64];         // mlp1 per-block partials [64 blk][sum32|sq32]
__device__ float g_p2[64 * 128];        // mlp3 per-block partials [64 blk][sum64|sq64]
__device__ int   g_fps[16384];          // [B, 2048]
__device__ float g_pooled[16384 * 67];  // [B*S, 67]
__device__ float g_y3[16384 * 64];      // conv3 output [B*S, 64]

// ---------------- packed f32x2 helpers (per-lane .rn == scalar .rn) ----------------
__device__ __forceinline__ unsigned long long f2_add(unsigned long long a, unsigned long long b) {
    unsigned long long r;
    asm("add.rn.f32x2 %0, %1, %2;" : "=l"(r) : "l"(a), "l"(b));
    return r;
}
__device__ __forceinline__ unsigned long long f2_mul(unsigned long long a, unsigned long long b) {
    unsigned long long r;
    asm("mul.rn.f32x2 %0, %1, %2;" : "=l"(r) : "l"(a), "l"(b));
    return r;
}
__device__ __forceinline__ unsigned long long f2_pack(float lo, float hi) {
    unsigned long long r;
    asm("mov.b64 %0, {%1, %2};" : "=l"(r) : "f"(lo), "f"(hi));
    return r;
}
__device__ __forceinline__ float2 f2_unpack(unsigned long long v) {
    float2 f;
    asm("mov.b64 {%0, %1}, %2;" : "=f"(f.x), "=f"(f.y) : "l"(v));
    return f;
}

// ---------------- fused FPS (blocks 0-7) + mlp1 (blocks 8-71) ----------------
__global__ void __launch_bounds__(512, 1)
fps_mlp1_kernel(const float* __restrict__ x, const float* __restrict__ W1,
                const float* __restrict__ b1) {
    if (blockIdx.x < 8) {
        // ======== FPS: 512 threads, 8 pts/thread (4 packed pairs), 1 barrier/step
        extern __shared__ float4 pts[];            // [4096] = 64KB
        __shared__ unsigned rv[2][16], ri[2][16];
        int b = blockIdx.x, tid = threadIdx.x;
        int lane = tid & 31, warp = tid >> 5;
        const float* xb = x + b * 12288;

        unsigned long long PX[4], PY[4], PZ[4];
        float dd[8];
        #pragma unroll
        for (int k = 0; k < 4; k++) {
            int i = 2 * tid + 1024 * k;
            float x0 = xb[3 * i],     y0 = xb[3 * i + 1], z0 = xb[3 * i + 2];
            float x1 = xb[3 * i + 3], y1 = xb[3 * i + 4], z1 = xb[3 * i + 5];
            pts[i]     = make_float4(x0, y0, z0, 0.0f);
            pts[i + 1] = make_float4(x1, y1, z1, 0.0f);
            PX[k] = f2_pack(x0, x1); PY[k] = f2_pack(y0, y1); PZ[k] = f2_pack(z0, z1);
            dd[2 * k] = FLTMAX; dd[2 * k + 1] = FLTMAX;
        }
        __syncthreads();

        int far = 0;
        int* outp = g_fps + b * 2048;

        for (int s = 0; s < 2048; s++) {
            if (tid == 0) outp[s] = far;
            float4 c = pts[far];
            unsigned long long ncx = f2_pack(-c.x, -c.x);
            unsigned long long ncy = f2_pack(-c.y, -c.y);
            unsigned long long ncz = f2_pack(-c.z, -c.z);
            #pragma unroll
            for (int k = 0; k < 4; k++) {
                unsigned long long dx = f2_add(PX[k], ncx);
                unsigned long long dy = f2_add(PY[k], ncy);
                unsigned long long dz = f2_add(PZ[k], ncz);
                unsigned long long d = f2_add(f2_add(f2_mul(dx, dx), f2_mul(dy, dy)),
                                              f2_mul(dz, dz));
                float2 f = f2_unpack(d);
                dd[2 * k]     = fminf(dd[2 * k], f.x);
                dd[2 * k + 1] = fminf(dd[2 * k + 1], f.y);
            }
            // local argmax in ascending global-index order (strict > keeps lowest idx)
            float bv = dd[0]; int bi = 2 * tid;
            #pragma unroll
            for (int k = 0; k < 4; k++) {
                int i = 2 * tid + 1024 * k;
                if (k > 0 && dd[2 * k] > bv) { bv = dd[2 * k]; bi = i; }
                if (dd[2 * k + 1] > bv) { bv = dd[2 * k + 1]; bi = i + 1; }
            }
            unsigned vb = __float_as_uint(bv);
            unsigned wm = __reduce_max_sync(0xffffffffu, vb);
            unsigned cand = (vb == wm) ? (unsigned)bi : 0xffffffffu;
            unsigned wi = __reduce_min_sync(0xffffffffu, cand);
            int p = s & 1;
            if (lane == 0) { rv[p][warp] = wm; ri[p][warp] = wi; }
            __syncthreads();
            // all warps reduce the 16 partials redundantly (lanes 16-31 mirror 0-15)
            unsigned v  = rv[p][lane & 15];
            unsigned i2 = ri[p][lane & 15];
            unsigned m2 = __reduce_max_sync(0xffffffffu, v);
            unsigned c2 = (v == m2) ? i2 : 0xffffffffu;
            far = (int)__reduce_min_sync(0xffffffffu, c2);
        }
    } else {
        // ======== mlp1: conv1 (3->32) + BN1 partial stats, 1 point/thread
        __shared__ float sW[96], sb[32], ssum[32], ssq[32];
        int tid = threadIdx.x;
        int blk = blockIdx.x - 8;
        if (tid < 96) sW[tid] = W1[tid];
        if (tid < 32) { sb[tid] = b1[tid]; ssum[tid] = 0.0f; ssq[tid] = 0.0f; }
        __syncthreads();
        int p = blk * 512 + tid;
        float X = x[3 * p], Y = x[3 * p + 1], Z = x[3 * p + 2];
        int lane = tid & 31;
        for (int c = 0; c < 32; c++) {
            float v = fmaf(sW[3 * c + 2], Z, fmaf(sW[3 * c + 1], Y, fmaf(sW[3 * c], X, sb[c])));
            g_y1[p * 32 + c] = v;
            float s = v, q = v * v;
            #pragma unroll
            for (int off = 16; off; off >>= 1) {
                s += __shfl_down_sync(0xffffffffu, s, off);
                q += __shfl_down_sync(0xffffffffu, q, off);
            }
            if (lane == 0) { atomicAdd(&ssum[c], s); atomicAdd(&ssq[c], q); }
        }
        __syncthreads();
        if (tid < 32) {
            g_p1[blk * 64 + tid] = ssum[tid];
            g_p1[blk * 64 + 32 + tid] = ssq[tid];
        }
    }
}

// ---------------- BN1 finalize (in-block) + ReLU + conv2 (32->64) ----------------
__global__ void mlp2_kernel(const float* __restrict__ W2, const float* __restrict__ b2,
                            const float* __restrict__ g1, const float* __restrict__ be1) {
    __shared__ float sW[2048], sb[64], sc[32], sh[32];
    int tid = threadIdx.x;
    for (int i = tid; i < 2048; i += 256) sW[i] = W2[i];
    if (tid < 64) sb[tid] = b2[tid];
    if (tid < 32) {
        float sum = 0.0f, sq = 0.0f;
        for (int k = 0; k < 64; k++) {
            sum += g_p1[k * 64 + tid];
            sq  += g_p1[k * 64 + 32 + tid];
        }
        const float n = 32768.0f;
        float mean = sum / n;
        float var  = sq / n - mean * mean;
        float scl  = g1[tid] * rsqrtf(var + 1e-5f);
        sc[tid] = scl;
        sh[tid] = be1[tid] - mean * scl;
    }
    __syncthreads();
    int p = blockIdx.x * 256 + tid;
    float t[32];
    #pragma unroll
    for (int c = 0; c < 32; c++)
        t[c] = fmaxf(fmaf(g_y1[p * 32 + c], sc[c], sh[c]), 0.0f);
    for (int o = 0; o < 64; o++) {
        float acc = sb[o];
        #pragma unroll
        for (int c = 0; c < 32; c++) acc = fmaf(sW[o * 32 + c], t[c], acc);
        g_feats[p * 64 + o] = acc;
    }
}

// ---------------- 16-NN + group + maxpool: 2 threads per query ----------------
__global__ void __launch_bounds__(128) knn_pool_kernel(const float* __restrict__ x) {
    __shared__ float sx[1024], sy[1024], sz[1024], sn[1024];  // tile (16KB)
    __shared__ float2 mg[2048];                               // merge scratch [64q][32]
    __shared__ int klist[64 * 16];                            // merged neighbor idx
    int b = blockIdx.y;
    int tid = threadIdx.x;
    int r = tid & 1;          // half-id within pair
    int ql = tid >> 1;        // local query 0..63
    int s = blockIdx.x * 64 + ql;
    const float* xb = x + b * 12288;
    int qi = g_fps[b * 2048 + s];
    float qx = xb[3 * qi], qy = xb[3 * qi + 1], qz = xb[3 * qi + 2];
    float qn = __fadd_rn(__fadd_rn(__fmul_rn(qx, qx), __fmul_rn(qy, qy)), __fmul_rn(qz, qz));
    unsigned long long qx2 = f2_pack(qx, qx), qy2 = f2_pack(qy, qy), qz2 = f2_pack(qz, qz);
    unsigned long long qn2 = f2_pack(qn, qn), n2 = f2_pack(-2.0f, -2.0f);

    float bd[16];
    int   bi[16];
    #pragma unroll
    for (int m = 0; m < 16; m++) { bd[m] = FLTMAX; bi[m] = 0x7fffffff; }
    float w = FLTMAX;
    int ws = 0;

    for (int t = 0; t < 4; t++) {
        __syncthreads();
        for (int j = tid; j < 1024; j += 128) {
            int i = t * 1024 + j;
            float X = xb[3 * i], Y = xb[3 * i + 1], Z = xb[3 * i + 2];
            sx[j] = X; sy[j] = Y; sz[j] = Z;
            sn[j] = __fadd_rn(__fadd_rn(__fmul_rn(X, X), __fmul_rn(Y, Y)), __fmul_rn(Z, Z));
        }
        __syncthreads();
        int half = r * 512;
        const float2* px2 = (const float2*)(sx + half);
        const float2* py2 = (const float2*)(sy + half);
        const float2* pz2 = (const float2*)(sz + half);
        const float2* pn2 = (const float2*)(sn + half);
        int base = t * 1024 + half;
        for (int j2 = 0; j2 < 256; j2++) {
            float2 vx = px2[j2], vy = py2[j2], vz = pz2[j2], vn = pn2[j2];
            unsigned long long dot = f2_add(f2_add(f2_mul(qx2, f2_pack(vx.x, vx.y)),
                                                   f2_mul(qy2, f2_pack(vy.x, vy.y))),
                                            f2_mul(qz2, f2_pack(vz.x, vz.y)));
            unsigned long long d2 = f2_add(f2_add(qn2, f2_pack(vn.x, vn.y)), f2_mul(dot, n2));
            float2 d = f2_unpack(d2);
            if (fminf(d.x, d.y) < w) {
                #pragma unroll
                for (int h = 0; h < 2; h++) {
                    float dv = h ? d.y : d.x;
                    if (dv < w) {
                        int i = base + 2 * j2 + h;
                        #pragma unroll
                        for (int m = 0; m < 16; m++)
                            if (m == ws) { bd[m] = dv; bi[m] = i; }
                        float nw = -FLTMAX; int nwi = -1; int nws = 0;
                        #pragma unroll
                        for (int m = 0; m < 16; m++) {
                            bool better = (bd[m] > nw) || (bd[m] == nw && bi[m] > nwi);
                            if (better) { nw = bd[m]; nwi = bi[m]; nws = m; }
                        }
                        w = nw; ws = nws;
                    }
                }
            }
        }
    }

    // ---- pair merge: write my 16 candidates, rank against union of 32 ----
    __syncthreads();   // tiles no longer needed; mg/klist are separate arrays
    #pragma unroll
    for (int m = 0; m < 16; m++)
        mg[ql * 32 + r * 16 + m] = make_float2(bd[m], __int_as_float(bi[m]));
    __syncwarp();
    const float2* pmg = &mg[ql * 32 + (r ^ 1) * 16];
    bool keep[16];
    int cnt = 0;
    #pragma unroll
    for (int m = 0; m < 16; m++) {
        int rank = 0;
        #pragma unroll
        for (int e = 0; e < 16; e++)
            rank += (bd[e] < bd[m]) || (bd[e] == bd[m] && bi[e] < bi[m]);
        for (int e = 0; e < 16; e++) {
            float2 pe = pmg[e];
            int pi = __float_as_int(pe.y);
            rank += (pe.x < bd[m]) || (pe.x == bd[m] && pi < bi[m]);
        }
        keep[m] = rank < 16;
        cnt += keep[m];
    }
    int pcnt = __shfl_xor_sync(0xffffffffu, cnt, 1);
    int off = r ? pcnt : 0;
    int* kl = &klist[ql * 16];
    #pragma unroll
    for (int m = 0; m < 16; m++)
        if (keep[m]) kl[off++] = bi[m];
    __syncwarp();

    // ---- xyz max (both threads redundantly over all 16) ----
    float mx = -FLTMAX, my = -FLTMAX, mz = -FLTMAX;
    int idx16[16];
    #pragma unroll
    for (int k = 0; k < 16; k++) idx16[k] = kl[k];
    #pragma unroll
    for (int k = 0; k < 16; k++) {
        int i = idx16[k];
        mx = fmaxf(mx, __fsub_rn(xb[3 * i], qx));
        my = fmaxf(my, __fsub_rn(xb[3 * i + 1], qy));
        mz = fmaxf(mz, __fsub_rn(xb[3 * i + 2], qz));
    }

    // ---- feature maxpool: pair splits 64 dims (32 each) ----
    const float* fb = g_feats + b * 4096 * 64 + r * 32;
    float4 acc[8];
    #pragma unroll
    for (int q = 0; q < 8; q++) acc[q] = make_float4(-FLTMAX, -FLTMAX, -FLTMAX, -FLTMAX);
    #pragma unroll
    for (int k = 0; k < 16; k++) {
        const float4* fr = (const float4*)(fb + idx16[k] * 64);
        #pragma unroll
        for (int q = 0; q < 8; q++) {
            float4 f = fr[q];
            acc[q].x = fmaxf(acc[q].x, f.x);
            acc[q].y = fmaxf(acc[q].y, f.y);
            acc[q].z = fmaxf(acc[q].z, f.z);
            acc[q].w = fmaxf(acc[q].w, f.w);
        }
    }
    float* op = g_pooled + (b * 2048 + s) * 67;
    if (r == 0) { op[0] = mx; op[1] = my; op[2] = mz; }
    float* of = op + 3 + r * 32;
    #pragma unroll
    for (int q = 0; q < 8; q++) {
        of[4 * q]     = acc[q].x;
        of[4 * q + 1] = acc[q].y;
        of[4 * q + 2] = acc[q].z;
        of[4 * q + 3] = acc[q].w;
    }
}

// ---------------- conv3 (67->64) + BN2 partial stats ----------------
__global__ void mlp3_kernel(const float* __restrict__ W3, const float* __restrict__ b3) {
    __shared__ float sW[64 * 67];
    __shared__ float sb[64], ssum[64], ssq[64];
    int tid = threadIdx.x;
    for (int i = tid; i < 4288; i += 256) sW[i] = W3[i];
    if (tid < 64) { sb[tid] = b3[tid]; ssum[tid] = 0.0f; ssq[tid] = 0.0f; }
    __syncthreads();
    int p = blockIdx.x * 256 + tid;
    float t[67];
    #pragma unroll
    for (int c = 0; c < 67; c++) t[c] = g_pooled[p * 67 + c];
    int lane = tid & 31;
    for (int o = 0; o < 64; o++) {
        float acc = sb[o];
        #pragma unroll
        for (int c = 0; c < 67; c++) acc = fmaf(sW[o * 67 + c], t[c], acc);
        g_y3[p * 64 + o] = acc;
        float sv = acc, sq = acc * acc;
        #pragma unroll
        for (int off = 16; off; off >>= 1) {
            sv += __shfl_down_sync(0xffffffffu, sv, off);
            sq += __shfl_down_sync(0xffffffffu, sq, off);
        }
        if (lane == 0) { atomicAdd(&ssum[o], sv); atomicAdd(&ssq[o], sq); }
    }
    __syncthreads();
    if (tid < 64) {
        g_p2[blockIdx.x * 128 + tid] = ssum[tid];
        g_p2[blockIdx.x * 128 + 64 + tid] = ssq[tid];
    }
}

// ---------------- BN2 finalize (in-block) + ReLU + conv4 (64->64) -> out ----------------
__global__ void mlp4_kernel(const float* __restrict__ W4, const float* __restrict__ b4,
                            const float* __restrict__ g2, const float* __restrict__ be2,
                            float* __restrict__ out) {
    __shared__ float sW[4096], sb[64], sc[64], sh[64];
    int tid = threadIdx.x;
    for (int i = tid; i < 4096; i += 256) sW[i] = W4[i];
    if (tid < 64) {
        sb[tid] = b4[tid];
        float sum = 0.0f, sq = 0.0f;
        for (int k = 0; k < 64; k++) {
            sum += g_p2[k * 128 + tid];
            sq  += g_p2[k * 128 + 64 + tid];
        }
        const float n = 16384.0f;
        float mean = sum / n;
        float var  = sq / n - mean * mean;
        float scl  = g2[tid] * rsqrtf(var + 1e-5f);
        sc[tid] = scl;
        sh[tid] = be2[tid] - mean * scl;
    }
    __syncthreads();
    int p = blockIdx.x * 256 + tid;
    float t[64];
    #pragma unroll
    for (int c = 0; c < 64; c++)
        t[c] = fmaxf(fmaf(g_y3[p * 64 + c], sc[c], sh[c]), 0.0f);
    for (int o = 0; o < 64; o++) {
        float acc = sb[o];
        #pragma unroll
        for (int c = 0; c < 64; c++) acc = fmaf(sW[o * 64 + c], t[c], acc);
        out[p * 64 + o] = acc;
    }
}

// ---------------- launch ----------------
extern "C" void kernel_launch(void* const* d_in, const int* in_sizes, int n_in,
                              void* d_out, int out_size) {
    const float* x   = (const float*)d_in[0];
    const float* W1  = (const float*)d_in[1];
    const float* b1  = (const float*)d_in[2];
    const float* g1  = (const float*)d_in[3];
    const float* be1 = (const float*)d_in[4];
    const float* W2  = (const float*)d_in[5];
    const float* b2  = (const float*)d_in[6];
    const float* W3  = (const float*)d_in[7];
    const float* b3  = (const float*)d_in[8];
    const float* g2  = (const float*)d_in[9];
    const float* be2 = (const float*)d_in[10];
    const float* W4  = (const float*)d_in[11];
    const float* b4  = (const float*)d_in[12];
    float* out = (float*)d_out;

    cudaFuncSetAttribute(fps_mlp1_kernel, cudaFuncAttributeMaxDynamicSharedMemorySize, 65536);

    fps_mlp1_kernel<<<72, 512, 65536>>>(x, W1, b1);  // FPS (8 CTAs) || mlp1 (64 CTAs)
    mlp2_kernel<<<128, 256>>>(W2, b2, g1, be1);
    knn_pool_kernel<<<dim3(32, 8), 128>>>(x);
    mlp3_kernel<<<64, 256>>>(W3, b3);
    mlp4_kernel<<<64, 256>>>(W4, b4, g2, be2, out);
}

// round 5
// speedup vs baseline: 1.6399x; 1.0869x over previous
#include <cuda_runtime.h>

#define FLTMAX 3.402823466e+38f

// ---------------- device scratch ----------------
__device__ float g_y1[32768 * 32];      // conv1 output [B*N, 32]
__device__ float g_feats[32768 * 64];   // conv2 output [B*N, 64]
__device__ float g_p1[128 * 64];        // mlp1 per-block partials [128 blk][sum32|sq32]
__device__ float g_p2[128 * 128];       // mlp3 per-block partials [128 blk][sum64|sq64]
__device__ int   g_fps[16384];          // [B, 2048]
__device__ float g_pooled[16384 * 68];  // [B*S][feat64 | xyz3 | pad] (68 = 17 float4)
__device__ float g_y3[16384 * 64];      // conv3 output [B*S, 64]

// ---------------- packed f32x2 helpers (per-lane .rn == scalar .rn) ----------------
__device__ __forceinline__ unsigned long long f2_add(unsigned long long a, unsigned long long b) {
    unsigned long long r;
    asm("add.rn.f32x2 %0, %1, %2;" : "=l"(r) : "l"(a), "l"(b));
    return r;
}
__device__ __forceinline__ unsigned long long f2_mul(unsigned long long a, unsigned long long b) {
    unsigned long long r;
    asm("mul.rn.f32x2 %0, %1, %2;" : "=l"(r) : "l"(a), "l"(b));
    return r;
}
__device__ __forceinline__ unsigned long long f2_pack(float lo, float hi) {
    unsigned long long r;
    asm("mov.b64 %0, {%1, %2};" : "=l"(r) : "f"(lo), "f"(hi));
    return r;
}
__device__ __forceinline__ float2 f2_unpack(unsigned long long v) {
    float2 f;
    asm("mov.b64 {%0, %1}, %2;" : "=f"(f.x), "=f"(f.y) : "l"(v));
    return f;
}

// ---------------- fused FPS (blocks 0-7) + mlp1 (blocks 8-135) ----------------
__global__ void __launch_bounds__(256, 1)
fps_mlp1_kernel(const float* __restrict__ x, const float* __restrict__ W1,
                const float* __restrict__ b1) {
    if (blockIdx.x < 8) {
        // ======== FPS: 256 threads, 16 pts/thread (8 packed pairs), 1 barrier/step
        extern __shared__ float4 pts[];            // [4096] = 64KB
        __shared__ unsigned rv[2][8], ri[2][8];
        int b = blockIdx.x, tid = threadIdx.x;
        int lane = tid & 31, warp = tid >> 5;
        const float* xb = x + b * 12288;

        // store NEGATED points in registers: dx = c + (-p); (-t)^2 == t^2 exactly
        unsigned long long NX[8], NY[8], NZ[8];
        float dd[16];
        #pragma unroll
        for (int k = 0; k < 8; k++) {
            int i = 2 * tid + 512 * k;
            float x0 = xb[3 * i],     y0 = xb[3 * i + 1], z0 = xb[3 * i + 2];
            float x1 = xb[3 * i + 3], y1 = xb[3 * i + 4], z1 = xb[3 * i + 5];
            pts[i]     = make_float4(x0, y0, z0, 0.0f);
            pts[i + 1] = make_float4(x1, y1, z1, 0.0f);
            NX[k] = f2_pack(-x0, -x1); NY[k] = f2_pack(-y0, -y1); NZ[k] = f2_pack(-z0, -z1);
            dd[2 * k] = FLTMAX; dd[2 * k + 1] = FLTMAX;
        }
        __syncthreads();

        int far = 0;
        int* outp = g_fps + b * 2048;

        for (int s = 0; s < 2048; s++) {
            if (tid == 0) outp[s] = far;
            float4 c = pts[far];
            unsigned long long cx = f2_pack(c.x, c.x);
            unsigned long long cy = f2_pack(c.y, c.y);
            unsigned long long cz = f2_pack(c.z, c.z);
            #pragma unroll
            for (int k = 0; k < 8; k++) {
                unsigned long long dx = f2_add(NX[k], cx);
                unsigned long long dy = f2_add(NY[k], cy);
                unsigned long long dz = f2_add(NZ[k], cz);
                unsigned long long d = f2_add(f2_add(f2_mul(dx, dx), f2_mul(dy, dy)),
                                              f2_mul(dz, dz));
                float2 f = f2_unpack(d);
                dd[2 * k]     = fminf(dd[2 * k], f.x);
                dd[2 * k + 1] = fminf(dd[2 * k + 1], f.y);
            }
            // local argmax in ascending global-index order (strict > keeps lowest idx)
            float bv = dd[0]; int bi = 2 * tid;
            #pragma unroll
            for (int k = 0; k < 8; k++) {
                int i = 2 * tid + 512 * k;
                if (k > 0 && dd[2 * k] > bv) { bv = dd[2 * k]; bi = i; }
                if (dd[2 * k + 1] > bv) { bv = dd[2 * k + 1]; bi = i + 1; }
            }
            unsigned vb = __float_as_uint(bv);
            unsigned wm = __reduce_max_sync(0xffffffffu, vb);
            unsigned cand = (vb == wm) ? (unsigned)bi : 0xffffffffu;
            unsigned wi = __reduce_min_sync(0xffffffffu, cand);
            int p = s & 1;
            if (lane == 0) { rv[p][warp] = wm; ri[p][warp] = wi; }
            __syncthreads();
            unsigned v  = rv[p][lane & 7];
            unsigned i2 = ri[p][lane & 7];
            unsigned m2 = __reduce_max_sync(0xffffffffu, v);
            unsigned c2 = (v == m2) ? i2 : 0xffffffffu;
            far = (int)__reduce_min_sync(0xffffffffu, c2);
        }
    } else {
        // ======== mlp1: conv1 (3->32) + BN1 partial stats, 1 point/thread
        __shared__ float sW[96], sb[32], ssum[32], ssq[32];
        int tid = threadIdx.x;
        int blk = blockIdx.x - 8;
        if (tid < 96) sW[tid] = W1[tid];
        if (tid < 32) { sb[tid] = b1[tid]; ssum[tid] = 0.0f; ssq[tid] = 0.0f; }
        __syncthreads();
        int p = blk * 256 + tid;
        float X = x[3 * p], Y = x[3 * p + 1], Z = x[3 * p + 2];
        int lane = tid & 31;
        for (int c = 0; c < 32; c++) {
            float v = fmaf(sW[3 * c + 2], Z, fmaf(sW[3 * c + 1], Y, fmaf(sW[3 * c], X, sb[c])));
            g_y1[p * 32 + c] = v;
            float s = v, q = v * v;
            #pragma unroll
            for (int off = 16; off; off >>= 1) {
                s += __shfl_down_sync(0xffffffffu, s, off);
                q += __shfl_down_sync(0xffffffffu, q, off);
            }
            if (lane == 0) { atomicAdd(&ssum[c], s); atomicAdd(&ssq[c], q); }
        }
        __syncthreads();
        if (tid < 32) {
            g_p1[blk * 64 + tid] = ssum[tid];
            g_p1[blk * 64 + 32 + tid] = ssq[tid];
        }
    }
}

// ---------------- BN1 finalize (in-block) + ReLU + conv2 (32->64) ----------------
__global__ void __launch_bounds__(128) mlp2_kernel(const float* __restrict__ W2,
                                                   const float* __restrict__ b2,
                                                   const float* __restrict__ g1,
                                                   const float* __restrict__ be1) {
    __shared__ float sW[2048], sb[64], sc[32], sh[32];
    int tid = threadIdx.x;
    for (int i = tid; i < 2048; i += 128) sW[i] = W2[i];
    if (tid < 64) sb[tid] = b2[tid];
    if (tid < 32) {
        float sum = 0.0f, sq = 0.0f;
        for (int k = 0; k < 128; k++) {
            sum += g_p1[k * 64 + tid];
            sq  += g_p1[k * 64 + 32 + tid];
        }
        const float n = 32768.0f;
        float mean = sum / n;
        float var  = sq / n - mean * mean;
        float scl  = g1[tid] * rsqrtf(var + 1e-5f);
        sc[tid] = scl;
        sh[tid] = be1[tid] - mean * scl;
    }
    __syncthreads();
    int p = blockIdx.x * 128 + tid;
    float t[32];
    const float4* yin = (const float4*)(g_y1 + p * 32);
    #pragma unroll
    for (int q = 0; q < 8; q++) {
        float4 v = yin[q];
        t[4 * q]     = fmaxf(fmaf(v.x, sc[4 * q],     sh[4 * q]),     0.0f);
        t[4 * q + 1] = fmaxf(fmaf(v.y, sc[4 * q + 1], sh[4 * q + 1]), 0.0f);
        t[4 * q + 2] = fmaxf(fmaf(v.z, sc[4 * q + 2], sh[4 * q + 2]), 0.0f);
        t[4 * q + 3] = fmaxf(fmaf(v.w, sc[4 * q + 3], sh[4 * q + 3]), 0.0f);
    }
    for (int o = 0; o < 64; o++) {
        float acc = sb[o];
        #pragma unroll
        for (int c = 0; c < 32; c++) acc = fmaf(sW[o * 32 + c], t[c], acc);
        g_feats[p * 64 + o] = acc;
    }
}

// ---------------- 16-NN + group + maxpool: 4 threads per query ----------------
// Quarters padded to stride 264 (bank-conflict-free); rank-merge of 4x16 lists.
__global__ void __launch_bounds__(128) knn_pool_kernel(const float* __restrict__ x) {
    __shared__ float sx[1056], sy[1056], sz[1056], sn[1056];
    __shared__ float2 mg[32 * 64];       // candidate union per query
    __shared__ int klist[32 * 16];       // merged neighbor idx (sorted by rank)
    int b = blockIdx.y;
    int tid = threadIdx.x;
    int r = tid & 3;          // quarter id
    int ql = tid >> 2;        // local query 0..31
    int s = blockIdx.x * 32 + ql;
    const float* xb = x + b * 12288;
    int qi = g_fps[b * 2048 + s];
    float qx = xb[3 * qi], qy = xb[3 * qi + 1], qz = xb[3 * qi + 2];
    float qn = __fadd_rn(__fadd_rn(__fmul_rn(qx, qx), __fmul_rn(qy, qy)), __fmul_rn(qz, qz));
    unsigned long long qx2 = f2_pack(qx, qx), qy2 = f2_pack(qy, qy), qz2 = f2_pack(qz, qz);
    unsigned long long qn2 = f2_pack(qn, qn), n2 = f2_pack(-2.0f, -2.0f);

    float bd[16];
    int   bi[16];
    #pragma unroll
    for (int m = 0; m < 16; m++) { bd[m] = FLTMAX; bi[m] = 0x7fffffff; }
    float w = FLTMAX;
    int ws = 0;

    for (int t = 0; t < 4; t++) {
        __syncthreads();
        for (int j = tid; j < 1024; j += 128) {
            int i = t * 1024 + j;
            int slot = (j >> 8) * 264 + (j & 255);
            float X = xb[3 * i], Y = xb[3 * i + 1], Z = xb[3 * i + 2];
            sx[slot] = X; sy[slot] = Y; sz[slot] = Z;
            sn[slot] = __fadd_rn(__fadd_rn(__fmul_rn(X, X), __fmul_rn(Y, Y)), __fmul_rn(Z, Z));
        }
        __syncthreads();
        int qbase = r * 264;
        const float2* px2 = (const float2*)(sx + qbase);
        const float2* py2 = (const float2*)(sy + qbase);
        const float2* pz2 = (const float2*)(sz + qbase);
        const float2* pn2 = (const float2*)(sn + qbase);
        int base = t * 1024 + r * 256;
        for (int j2 = 0; j2 < 128; j2++) {
            float2 vx = px2[j2], vy = py2[j2], vz = pz2[j2], vn = pn2[j2];
            unsigned long long dot = f2_add(f2_add(f2_mul(qx2, f2_pack(vx.x, vx.y)),
                                                   f2_mul(qy2, f2_pack(vy.x, vy.y))),
                                            f2_mul(qz2, f2_pack(vz.x, vz.y)));
            unsigned long long d2 = f2_add(f2_add(qn2, f2_pack(vn.x, vn.y)), f2_mul(dot, n2));
            float2 d = f2_unpack(d2);
            if (fminf(d.x, d.y) < w) {
                #pragma unroll
                for (int h = 0; h < 2; h++) {
                    float dv = h ? d.y : d.x;
                    if (dv < w) {
                        int i = base + 2 * j2 + h;
                        #pragma unroll
                        for (int m = 0; m < 16; m++)
                            if (m == ws) { bd[m] = dv; bi[m] = i; }
                        // rescan: worst = max dist, tie -> larger index (evicted first)
                        float nw = -FLTMAX; int nwi = -1; int nws = 0;
                        #pragma unroll
                        for (int m = 0; m < 16; m++) {
                            bool better = (bd[m] > nw) || (bd[m] == nw && bi[m] > nwi);
                            if (better) { nw = bd[m]; nwi = bi[m]; nws = m; }
                        }
                        w = nw; ws = nws;
                    }
                }
            }
        }
    }

    // ---- 4-way rank merge over disjoint-index union of 64 candidates ----
    __syncthreads();
    #pragma unroll
    for (int m = 0; m < 16; m++)
        mg[ql * 64 + r * 16 + m] = make_float2(bd[m], __int_as_float(bi[m]));
    __syncwarp();
    int rank[16];
    #pragma unroll
    for (int m = 0; m < 16; m++) rank[m] = 0;
    const float2* u = &mg[ql * 64];
    for (int e = 0; e < 64; e++) {
        float2 pe = u[e];
        int pi = __float_as_int(pe.y);
        #pragma unroll
        for (int m = 0; m < 16; m++)
            rank[m] += (pe.x < bd[m]) || (pe.x == bd[m] && pi < bi[m]);
    }
    int* kl = &klist[ql * 16];
    #pragma unroll
    for (int m = 0; m < 16; m++)
        if (rank[m] < 16) kl[rank[m]] = bi[m];
    __syncwarp();

    int idx16[16];
    #pragma unroll
    for (int k = 0; k < 16; k++) idx16[k] = kl[k];

    float* op = g_pooled + (b * 2048 + s) * 68;

    // ---- xyz max (thread r==0 only) ----
    if (r == 0) {
        float mx = -FLTMAX, my = -FLTMAX, mz = -FLTMAX;
        #pragma unroll
        for (int k = 0; k < 16; k++) {
            int i = idx16[k];
            mx = fmaxf(mx, __fsub_rn(xb[3 * i], qx));
            my = fmaxf(my, __fsub_rn(xb[3 * i + 1], qy));
            mz = fmaxf(mz, __fsub_rn(xb[3 * i + 2], qz));
        }
        op[64] = mx; op[65] = my; op[66] = mz; op[67] = 0.0f;
    }

    // ---- feature maxpool: each thread takes 16 dims ----
    const float* fb = g_feats + b * 4096 * 64 + r * 16;
    float4 acc[4];
    #pragma unroll
    for (int q = 0; q < 4; q++) acc[q] = make_float4(-FLTMAX, -FLTMAX, -FLTMAX, -FLTMAX);
    #pragma unroll
    for (int k = 0; k < 16; k++) {
        const float4* fr = (const float4*)(fb + idx16[k] * 64);
        #pragma unroll
        for (int q = 0; q < 4; q++) {
            float4 f = fr[q];
            acc[q].x = fmaxf(acc[q].x, f.x);
            acc[q].y = fmaxf(acc[q].y, f.y);
            acc[q].z = fmaxf(acc[q].z, f.z);
            acc[q].w = fmaxf(acc[q].w, f.w);
        }
    }
    float4* of = (float4*)(op + r * 16);
    #pragma unroll
    for (int q = 0; q < 4; q++) of[q] = acc[q];
}

// ---------------- conv3 (67->64, features-first layout) + BN2 partials ----------------
__global__ void __launch_bounds__(128) mlp3_kernel(const float* __restrict__ W3,
                                                   const float* __restrict__ b3) {
    __shared__ float sW[64 * 67];
    __shared__ float sb[64], ssum[64], ssq[64];
    int tid = threadIdx.x;
    for (int i = tid; i < 4288; i += 128) sW[i] = W3[i];
    if (tid < 64) { sb[tid] = b3[tid]; ssum[tid] = 0.0f; ssq[tid] = 0.0f; }
    __syncthreads();
    int p = blockIdx.x * 128 + tid;
    float t[68];
    const float4* pin = (const float4*)(g_pooled + p * 68);
    #pragma unroll
    for (int q = 0; q < 17; q++) {
        float4 v = pin[q];
        t[4 * q] = v.x; t[4 * q + 1] = v.y; t[4 * q + 2] = v.z; t[4 * q + 3] = v.w;
    }
    int lane = tid & 31;
    for (int o = 0; o < 64; o++) {
        // row layout: t[0..63]=feats (W cols 3..66), t[64..66]=xyz (W cols 0..2)
        float acc = sb[o];
        acc = fmaf(sW[o * 67 + 0], t[64], acc);
        acc = fmaf(sW[o * 67 + 1], t[65], acc);
        acc = fmaf(sW[o * 67 + 2], t[66], acc);
        #pragma unroll
        for (int c = 0; c < 64; c++) acc = fmaf(sW[o * 67 + 3 + c], t[c], acc);
        g_y3[p * 64 + o] = acc;
        float sv = acc, sq = acc * acc;
        #pragma unroll
        for (int off = 16; off; off >>= 1) {
            sv += __shfl_down_sync(0xffffffffu, sv, off);
            sq += __shfl_down_sync(0xffffffffu, sq, off);
        }
        if (lane == 0) { atomicAdd(&ssum[o], sv); atomicAdd(&ssq[o], sq); }
    }
    __syncthreads();
    if (tid < 64) {
        g_p2[blockIdx.x * 128 + tid] = ssum[tid];
        g_p2[blockIdx.x * 128 + 64 + tid] = ssq[tid];
    }
}

// ---------------- BN2 finalize (in-block) + ReLU + conv4 (64->64) -> out ----------------
__global__ void __launch_bounds__(128) mlp4_kernel(const float* __restrict__ W4,
                                                   const float* __restrict__ b4,
                                                   const float* __restrict__ g2,
                                                   const float* __restrict__ be2,
                                                   float* __restrict__ out) {
    __shared__ float sW[4096], sb[64], sc[64], sh[64];
    int tid = threadIdx.x;
    for (int i = tid; i < 4096; i += 128) sW[i] = W4[i];
    if (tid < 64) {
        sb[tid] = b4[tid];
        float sum = 0.0f, sq = 0.0f;
        for (int k = 0; k < 128; k++) {
            sum += g_p2[k * 128 + tid];
            sq  += g_p2[k * 128 + 64 + tid];
        }
        const float n = 16384.0f;
        float mean = sum / n;
        float var  = sq / n - mean * mean;
        float scl  = g2[tid] * rsqrtf(var + 1e-5f);
        sc[tid] = scl;
        sh[tid] = be2[tid] - mean * scl;
    }
    __syncthreads();
    int p = blockIdx.x * 128 + tid;
    float t[64];
    const float4* yin = (const float4*)(g_y3 + p * 64);
    #pragma unroll
    for (int q = 0; q < 16; q++) {
        float4 v = yin[q];
        t[4 * q]     = fmaxf(fmaf(v.x, sc[4 * q],     sh[4 * q]),     0.0f);
        t[4 * q + 1] = fmaxf(fmaf(v.y, sc[4 * q + 1], sh[4 * q + 1]), 0.0f);
        t[4 * q + 2] = fmaxf(fmaf(v.z, sc[4 * q + 2], sh[4 * q + 2]), 0.0f);
        t[4 * q + 3] = fmaxf(fmaf(v.w, sc[4 * q + 3], sh[4 * q + 3]), 0.0f);
    }
    for (int o = 0; o < 64; o++) {
        float acc = sb[o];
        #pragma unroll
        for (int c = 0; c < 64; c++) acc = fmaf(sW[o * 64 + c], t[c], acc);
        out[p * 64 + o] = acc;
    }
}

// ---------------- launch ----------------
extern "C" void kernel_launch(void* const* d_in, const int* in_sizes, int n_in,
                              void* d_out, int out_size) {
    const float* x   = (const float*)d_in[0];
    const float* W1  = (const float*)d_in[1];
    const float* b1  = (const float*)d_in[2];
    const float* g1  = (const float*)d_in[3];
    const float* be1 = (const float*)d_in[4];
    const float* W2  = (const float*)d_in[5];
    const float* b2  = (const float*)d_in[6];
    const float* W3  = (const float*)d_in[7];
    const float* b3  = (const float*)d_in[8];
    const float* g2  = (const float*)d_in[9];
    const float* be2 = (const float*)d_in[10];
    const float* W4  = (const float*)d_in[11];
    const float* b4  = (const float*)d_in[12];
    float* out = (float*)d_out;

    cudaFuncSetAttribute(fps_mlp1_kernel, cudaFuncAttributeMaxDynamicSharedMemorySize, 65536);

    fps_mlp1_kernel<<<136, 256, 65536>>>(x, W1, b1);  // FPS (8 CTAs) || mlp1 (128 CTAs)
    mlp2_kernel<<<256, 128>>>(W2, b2, g1, be1);
    knn_pool_kernel<<<dim3(64, 8), 128>>>(x);
    mlp3_kernel<<<128, 128>>>(W3, b3);
    mlp4_kernel<<<128, 128>>>(W4, b4, g2, be2, out);
}

// round 7
// speedup vs baseline: 1.6524x; 1.0076x over previous
#include <cuda_runtime.h>

#define FLTMAX 3.402823466e+38f

// ---------------- device scratch ----------------
__device__ float g_y1[32768 * 32];      // conv1 output [B*N, 32]
__device__ float g_feats[32768 * 64];   // conv2 output [B*N, 64]
__device__ float g_p1[128 * 64];        // mlp1 item partials [128][sum32|sq32]
__device__ float g_p2[256 * 128];       // mlp3 block partials [256][sum64|sq64]
__device__ float g_bn2[128];            // BN2 scale/shift
__device__ int   g_fps[16384];          // [B, 2048]
__device__ float g_pooled[16384 * 68];  // [B*S][feat64 | xyz3 | pad]
__device__ float g_y3[16384 * 64];      // conv3 output [B*S, 64]

// ---------------- control state (re-zeroed each launch by init kernel) ----
__device__ int g_q;            // work-queue head
__device__ int g_done1;        // mlp1 items finished (target 128)
__device__ int g_done2;        // mlp2 items finished (target 256)
__device__ int g_smid_ready;   // how many FPS CTAs published their smid
__device__ int g_prog[8];      // FPS progress per batch (# indices written)
__device__ int g_fps_sm[8];    // smid of each FPS CTA

__global__ void init_kernel() {
    int t = threadIdx.x;
    if (t == 0) { g_q = 0; g_done1 = 0; g_done2 = 0; g_smid_ready = 0; }
    if (t < 8) g_prog[t] = 0;
}

// ---------------- packed f32x2 helpers (per-lane .rn == scalar .rn) ----------------
__device__ __forceinline__ unsigned long long f2_add(unsigned long long a, unsigned long long b) {
    unsigned long long r;
    asm("add.rn.f32x2 %0, %1, %2;" : "=l"(r) : "l"(a), "l"(b));
    return r;
}
__device__ __forceinline__ unsigned long long f2_mul(unsigned long long a, unsigned long long b) {
    unsigned long long r;
    asm("mul.rn.f32x2 %0, %1, %2;" : "=l"(r) : "l"(a), "l"(b));
    return r;
}
__device__ __forceinline__ unsigned long long f2_pack(float lo, float hi) {
    unsigned long long r;
    asm("mov.b64 %0, {%1, %2};" : "=l"(r) : "f"(lo), "f"(hi));
    return r;
}
__device__ __forceinline__ float2 f2_unpack(unsigned long long v) {
    float2 f;
    asm("mov.b64 {%0, %1}, %2;" : "=f"(f.x), "=f"(f.y) : "l"(v));
    return f;
}

// =================================================================
// MEGA KERNEL: FPS (CTAs 0-7) + work-queue workers (mlp1, mlp2, knn)
// queue: [0,128) mlp1 (256 pts each) -> [128,384) mlp2 (128 pts each)
//        -> [384,640) knn (64 queries each)
// =================================================================
__global__ void __launch_bounds__(256, 2)
mega_kernel(const float* __restrict__ x,
            const float* __restrict__ W1, const float* __restrict__ b1,
            const float* __restrict__ W2, const float* __restrict__ b2,
            const float* __restrict__ g1, const float* __restrict__ be1) {
    extern __shared__ char smraw[];
    int tid = threadIdx.x;

    if (blockIdx.x < 8) {
        // ======================= FPS: one CTA per batch =======================
        float* px = (float*)smraw;           // [4096]
        float* py = px + 4096;
        float* pz = py + 4096;
        __shared__ unsigned rv[2][8], ri[2][8];
        int b = blockIdx.x;
        int lane = tid & 31, warp = tid >> 5;
        const float* xb = x + b * 12288;

        if (tid == 0) {
            unsigned sm_;
            asm("mov.u32 %0, %%smid;" : "=r"(sm_));
            g_fps_sm[b] = (int)sm_;
            __threadfence();
            atomicAdd(&g_smid_ready, 1);
        }

        // negated points in registers: dx = c + (-p); (-t)^2 == t^2 exactly
        unsigned long long NX[8], NY[8], NZ[8];
        float dd[16];
        #pragma unroll
        for (int k = 0; k < 8; k++) {
            int i = 2 * tid + 512 * k;
            float x0 = xb[3 * i],     y0 = xb[3 * i + 1], z0 = xb[3 * i + 2];
            float x1 = xb[3 * i + 3], y1 = xb[3 * i + 4], z1 = xb[3 * i + 5];
            px[i] = x0; py[i] = y0; pz[i] = z0;
            px[i + 1] = x1; py[i + 1] = y1; pz[i + 1] = z1;
            NX[k] = f2_pack(-x0, -x1); NY[k] = f2_pack(-y0, -y1); NZ[k] = f2_pack(-z0, -z1);
            dd[2 * k] = FLTMAX; dd[2 * k + 1] = FLTMAX;
        }
        __syncthreads();

        int far = 0;
        int* outp = g_fps + b * 2048;

        for (int s = 0; s < 2048; s++) {
            if (tid == 0) outp[s] = far;
            float cxs = px[far], cys = py[far], czs = pz[far];
            unsigned long long cx = f2_pack(cxs, cxs);
            unsigned long long cy = f2_pack(cys, cys);
            unsigned long long cz = f2_pack(czs, czs);
            #pragma unroll
            for (int k = 0; k < 8; k++) {
                unsigned long long dx = f2_add(NX[k], cx);
                unsigned long long dy = f2_add(NY[k], cy);
                unsigned long long dz = f2_add(NZ[k], cz);
                unsigned long long d = f2_add(f2_add(f2_mul(dx, dx), f2_mul(dy, dy)),
                                              f2_mul(dz, dz));
                float2 f = f2_unpack(d);
                dd[2 * k]     = fminf(dd[2 * k], f.x);
                dd[2 * k + 1] = fminf(dd[2 * k + 1], f.y);
            }
            // tree argmax over 16 slots (slot order == ascending global index;
            // strict > keeps lowest index on ties)
            float tv[16]; int ts[16];
            #pragma unroll
            for (int i = 0; i < 16; i++) { tv[i] = dd[i]; ts[i] = i; }
            #pragma unroll
            for (int off = 8; off; off >>= 1)
                #pragma unroll
                for (int i = 0; i < off; i++)
                    if (tv[i + off] > tv[i]) { tv[i] = tv[i + off]; ts[i] = ts[i + off]; }
            int slot = ts[0];
            int bi = 2 * tid + 512 * (slot >> 1) + (slot & 1);
            unsigned vb = __float_as_uint(tv[0]);

            unsigned wm = __reduce_max_sync(0xffffffffu, vb);
            unsigned cand = (vb == wm) ? (unsigned)bi : 0xffffffffu;
            unsigned wi = __reduce_min_sync(0xffffffffu, cand);
            int p = s & 1;
            if (lane == 0) { rv[p][warp] = wm; ri[p][warp] = wi; }
            __syncthreads();
            unsigned v  = rv[p][lane & 7];
            unsigned i2 = ri[p][lane & 7];
            unsigned m2 = __reduce_max_sync(0xffffffffu, v);
            unsigned c2 = (v == m2) ? i2 : 0xffffffffu;
            far = (int)__reduce_min_sync(0xffffffffu, c2);

            if (tid == 0 && (s & 31) == 31) {
                __threadfence();
                *(volatile int*)&g_prog[b] = s + 1;
            }
        }
        return;
    }

    // ======================= WORKERS =======================
    {
        unsigned mysm;
        asm("mov.u32 %0, %%smid;" : "=r"(mysm));
        while (*(volatile int*)&g_smid_ready < 8) __nanosleep(64);
        bool onfps = false;
        #pragma unroll
        for (int i = 0; i < 8; i++) onfps |= (g_fps_sm[i] == (int)mysm);
        if (onfps) return;   // keep FPS SMs uncontended
    }

    __shared__ int s_item;
    for (;;) {
        if (tid == 0) s_item = atomicAdd(&g_q, 1);
        __syncthreads();
        int it = s_item;
        __syncthreads();
        if (it >= 640) return;

        if (it < 128) {
            // ---------- mlp1 item: conv1(3->32)+BN1 partials, 256 pts ----------
            __shared__ float sW1[96], sb1[32], ssum[32], ssq[32];
            if (tid < 96) sW1[tid] = W1[tid];
            if (tid < 32) { sb1[tid] = b1[tid]; ssum[tid] = 0.0f; ssq[tid] = 0.0f; }
            __syncthreads();
            int p = it * 256 + tid;
            float X = x[3 * p], Y = x[3 * p + 1], Z = x[3 * p + 2];
            int lane = tid & 31;
            for (int c = 0; c < 32; c++) {
                float v = fmaf(sW1[3 * c + 2], Z,
                          fmaf(sW1[3 * c + 1], Y, fmaf(sW1[3 * c], X, sb1[c])));
                g_y1[p * 32 + c] = v;
                float sv = v, sq = v * v;
                #pragma unroll
                for (int off = 16; off; off >>= 1) {
                    sv += __shfl_down_sync(0xffffffffu, sv, off);
                    sq += __shfl_down_sync(0xffffffffu, sq, off);
                }
                if (lane == 0) { atomicAdd(&ssum[c], sv); atomicAdd(&ssq[c], sq); }
            }
            __syncthreads();
            if (tid < 32) {
                g_p1[it * 64 + tid] = ssum[tid];
                g_p1[it * 64 + 32 + tid] = ssq[tid];
            }
            __threadfence();
            __syncthreads();
            if (tid == 0) atomicAdd(&g_done1, 1);
        } else if (it < 384) {
            // ---------- mlp2 item: BN1+ReLU+conv2(32->64), 128 pts, transposed ----------
            int j = it - 128;                        // 0..255 -> covers all 32768 pts
            float* y1t = (float*)smraw;              // [128*32]
            float* W2s = (float*)smraw + 4096;       // [64*36] padded
            __shared__ float sc1[32], sh1[32], sb2[64];
            if (tid == 0) { while (*(volatile int*)&g_done1 < 128) __nanosleep(64); }
            __syncthreads();
            __threadfence();
            if (tid < 32) {
                float sum = 0.0f, sq = 0.0f;
                for (int k = 0; k < 128; k++) {
                    sum += g_p1[k * 64 + tid];
                    sq  += g_p1[k * 64 + 32 + tid];
                }
                float mean = sum / 32768.0f;
                float var  = sq / 32768.0f - mean * mean;
                float scl  = g1[tid] * rsqrtf(var + 1e-5f);
                sc1[tid] = scl;
                sh1[tid] = be1[tid] - mean * scl;
            }
            if (tid < 64) sb2[tid] = b2[tid];
            for (int i = tid; i < 2048; i += 256) {
                int o = i >> 5, c = i & 31;
                W2s[o * 36 + c] = W2[i];
            }
            __syncthreads();
            int p0 = j * 128;
            for (int i = tid; i < 4096; i += 256) {
                int c = i & 31;
                y1t[i] = fmaxf(fmaf(g_y1[p0 * 32 + i], sc1[c], sh1[c]), 0.0f);
            }
            __syncthreads();
            int o = tid & 63, q = tid >> 6;
            float acc[32];
            #pragma unroll
            for (int p = 0; p < 32; p++) acc[p] = sb2[o];
            const float4* wr = (const float4*)(W2s + o * 36);
            #pragma unroll
            for (int c4 = 0; c4 < 8; c4++) {
                float4 w = wr[c4];
                #pragma unroll
                for (int p = 0; p < 32; p++) {
                    float4 v = *(const float4*)(y1t + (q * 32 + p) * 32 + c4 * 4);
                    acc[p] = fmaf(w.x, v.x, fmaf(w.y, v.y,
                             fmaf(w.z, v.z, fmaf(w.w, v.w, acc[p]))));
                }
            }
            #pragma unroll
            for (int p = 0; p < 32; p++)
                g_feats[(p0 + q * 32 + p) * 64 + o] = acc[p];
            __threadfence();
            __syncthreads();
            if (tid == 0) atomicAdd(&g_done2, 1);
        } else {
            // ---------- knn item: 64 queries, 4 threads/query ----------
            int k = it - 384;
            int b = k & 7, grp = k >> 3;
            int s0 = grp * 64;
            float* sx = (float*)smraw;           // [1056]
            float* sy = sx + 1056;
            float* sz = sy + 1056;
            float* snn = sz + 1056;
            float2* mg = (float2*)(smraw + 16896);   // [64*64]
            int* klist = (int*)(smraw + 49664);      // [64*16]

            if (tid == 0) { while (*(volatile int*)&g_prog[b] < s0 + 64) __nanosleep(128); }
            __syncthreads();
            __threadfence();

            int r = tid & 3, ql = tid >> 2;
            int s = s0 + ql;
            const float* xb = x + b * 12288;
            int qi = g_fps[b * 2048 + s];
            float qx = xb[3 * qi], qy = xb[3 * qi + 1], qz = xb[3 * qi + 2];
            float qn = __fadd_rn(__fadd_rn(__fmul_rn(qx, qx), __fmul_rn(qy, qy)),
                                 __fmul_rn(qz, qz));
            unsigned long long qx2 = f2_pack(qx, qx), qy2 = f2_pack(qy, qy);
            unsigned long long qz2 = f2_pack(qz, qz);
            unsigned long long qn2 = f2_pack(qn, qn), n2 = f2_pack(-2.0f, -2.0f);

            float bd[16];
            int   bi[16];
            #pragma unroll
            for (int m = 0; m < 16; m++) { bd[m] = FLTMAX; bi[m] = 0x7fffffff; }
            float w = FLTMAX;
            int ws = 0;

            for (int t = 0; t < 4; t++) {
                __syncthreads();
                for (int jj = tid; jj < 1024; jj += 256) {
                    int i = t * 1024 + jj;
                    int slotp = (jj >> 8) * 264 + (jj & 255);
                    float X = xb[3 * i], Y = xb[3 * i + 1], Z = xb[3 * i + 2];
                    sx[slotp] = X; sy[slotp] = Y; sz[slotp] = Z;
                    snn[slotp] = __fadd_rn(__fadd_rn(__fmul_rn(X, X), __fmul_rn(Y, Y)),
                                           __fmul_rn(Z, Z));
                }
                __syncthreads();
                int qbase = r * 264;
                const float2* px2 = (const float2*)(sx + qbase);
                const float2* py2 = (const float2*)(sy + qbase);
                const float2* pz2 = (const float2*)(sz + qbase);
                const float2* pn2 = (const float2*)(snn + qbase);
                int base = t * 1024 + r * 256;
                for (int j2 = 0; j2 < 128; j2++) {
                    float2 vx = px2[j2], vy = py2[j2], vz = pz2[j2], vn = pn2[j2];
                    unsigned long long dot = f2_add(f2_add(f2_mul(qx2, f2_pack(vx.x, vx.y)),
                                                           f2_mul(qy2, f2_pack(vy.x, vy.y))),
                                                    f2_mul(qz2, f2_pack(vz.x, vz.y)));
                    unsigned long long d2 = f2_add(f2_add(qn2, f2_pack(vn.x, vn.y)),
                                                   f2_mul(dot, n2));
                    float2 d = f2_unpack(d2);
                    if (fminf(d.x, d.y) < w) {
                        #pragma unroll
                        for (int h = 0; h < 2; h++) {
                            float dv = h ? d.y : d.x;
                            if (dv < w) {
                                int i = base + 2 * j2 + h;
                                #pragma unroll
                                for (int m = 0; m < 16; m++)
                                    if (m == ws) { bd[m] = dv; bi[m] = i; }
                                float nw = -FLTMAX; int nwi = -1; int nws = 0;
                                #pragma unroll
                                for (int m = 0; m < 16; m++) {
                                    bool better = (bd[m] > nw) || (bd[m] == nw && bi[m] > nwi);
                                    if (better) { nw = bd[m]; nwi = bi[m]; nws = m; }
                                }
                                w = nw; ws = nws;
                            }
                        }
                    }
                }
            }

            // 4-way rank merge over disjoint-index union of 64 candidates
            __syncthreads();
            #pragma unroll
            for (int m = 0; m < 16; m++)
                mg[ql * 64 + r * 16 + m] = make_float2(bd[m], __int_as_float(bi[m]));
            __syncwarp();
            int rank[16];
            #pragma unroll
            for (int m = 0; m < 16; m++) rank[m] = 0;
            const float2* u = &mg[ql * 64];
            for (int e = 0; e < 64; e++) {
                float2 pe = u[e];
                int pi = __float_as_int(pe.y);
                #pragma unroll
                for (int m = 0; m < 16; m++)
                    rank[m] += (pe.x < bd[m]) || (pe.x == bd[m] && pi < bi[m]);
            }
            int* kl = &klist[ql * 16];
            #pragma unroll
            for (int m = 0; m < 16; m++)
                if (rank[m] < 16) kl[rank[m]] = bi[m];
            __syncwarp();

            int idx16[16];
            #pragma unroll
            for (int kk = 0; kk < 16; kk++) idx16[kk] = kl[kk];

            // wait for all feats before gather
            __syncthreads();
            if (tid == 0) { while (*(volatile int*)&g_done2 < 256) __nanosleep(128); }
            __syncthreads();
            __threadfence();

            float* op = g_pooled + (b * 2048 + s) * 68;
            if (r == 0) {
                float mx = -FLTMAX, my = -FLTMAX, mz = -FLTMAX;
                #pragma unroll
                for (int kk = 0; kk < 16; kk++) {
                    int i = idx16[kk];
                    mx = fmaxf(mx, __fsub_rn(xb[3 * i], qx));
                    my = fmaxf(my, __fsub_rn(xb[3 * i + 1], qy));
                    mz = fmaxf(mz, __fsub_rn(xb[3 * i + 2], qz));
                }
                op[64] = mx; op[65] = my; op[66] = mz; op[67] = 0.0f;
            }
            const float* fb = g_feats + b * 4096 * 64 + r * 16;
            float4 acc[4];
            #pragma unroll
            for (int q = 0; q < 4; q++)
                acc[q] = make_float4(-FLTMAX, -FLTMAX, -FLTMAX, -FLTMAX);
            #pragma unroll
            for (int kk = 0; kk < 16; kk++) {
                const float4* fr = (const float4*)(fb + idx16[kk] * 64);
                #pragma unroll
                for (int q = 0; q < 4; q++) {
                    float4 f = fr[q];
                    acc[q].x = fmaxf(acc[q].x, f.x);
                    acc[q].y = fmaxf(acc[q].y, f.y);
                    acc[q].z = fmaxf(acc[q].z, f.z);
                    acc[q].w = fmaxf(acc[q].w, f.w);
                }
            }
            float4* of = (float4*)(op + r * 16);
            #pragma unroll
            for (int q = 0; q < 4; q++) of[q] = acc[q];
            __syncthreads();
        }
    }
}

// ---------------- mlp3: conv3(67->64) transposed + BN2 partials ----------------
__global__ void __launch_bounds__(128) mlp3_kernel(const float* __restrict__ W3,
                                                   const float* __restrict__ b3) {
    __shared__ float P[64 * 68];
    __shared__ float W[64 * 68];
    __shared__ float sb[64];
    __shared__ float red[128];
    int tid = threadIdx.x;
    for (int i = tid; i < 64 * 68; i += 128) {
        int o = i / 68, c = i - o * 68;
        W[i] = (c < 64) ? W3[o * 67 + 3 + c] : ((c < 67) ? W3[o * 67 + (c - 64)] : 0.0f);
    }
    if (tid < 64) sb[tid] = b3[tid];
    int p0 = blockIdx.x * 64;
    for (int i = tid; i < 64 * 68; i += 128) P[i] = g_pooled[p0 * 68 + i];
    __syncthreads();
    int o = tid & 63, h = tid >> 6;
    float acc[32];
    #pragma unroll
    for (int p = 0; p < 32; p++) acc[p] = sb[o];
    const float4* wr = (const float4*)(W + o * 68);
    #pragma unroll
    for (int c4 = 0; c4 < 17; c4++) {
        float4 w = wr[c4];
        #pragma unroll
        for (int p = 0; p < 32; p++) {
            float4 v = *(const float4*)(P + (h * 32 + p) * 68 + c4 * 4);
            acc[p] = fmaf(w.x, v.x, fmaf(w.y, v.y, fmaf(w.z, v.z, fmaf(w.w, v.w, acc[p]))));
        }
    }
    float ssum = 0.0f, ssq = 0.0f;
    #pragma unroll
    for (int p = 0; p < 32; p++) {
        g_y3[(p0 + h * 32 + p) * 64 + o] = acc[p];
        ssum += acc[p]; ssq += acc[p] * acc[p];
    }
    red[tid] = ssum;
    __syncthreads();
    if (tid < 64) g_p2[blockIdx.x * 128 + tid] = red[tid] + red[tid + 64];
    __syncthreads();
    red[tid] = ssq;
    __syncthreads();
    if (tid < 64) g_p2[blockIdx.x * 128 + 64 + tid] = red[tid] + red[tid + 64];
}

// ---------------- BN2 finalize ----------------
__global__ void bnfin2_kernel(const float* __restrict__ g2, const float* __restrict__ be2) {
    int c = threadIdx.x;
    if (c >= 64) return;
    float sum = 0.0f, sq = 0.0f;
    for (int k = 0; k < 256; k++) {
        sum += g_p2[k * 128 + c];
        sq  += g_p2[k * 128 + 64 + c];
    }
    float mean = sum / 16384.0f;
    float var  = sq / 16384.0f - mean * mean;
    float scl  = g2[c] * rsqrtf(var + 1e-5f);
    g_bn2[c] = scl;
    g_bn2[64 + c] = be2[c] - mean * scl;
}

// ---------------- mlp4: BN2+ReLU+conv4(64->64) transposed -> out ----------------
__global__ void __launch_bounds__(128) mlp4_kernel(const float* __restrict__ W4,
                                                   const float* __restrict__ b4,
                                                   float* __restrict__ out) {
    __shared__ float Y[64 * 64];
    __shared__ float W[64 * 68];
    __shared__ float sb[64], sc[64], sh[64];
    int tid = threadIdx.x;
    if (tid < 64) { sb[tid] = b4[tid]; sc[tid] = g_bn2[tid]; sh[tid] = g_bn2[64 + tid]; }
    for (int i = tid; i < 64 * 68; i += 128) {
        int o = i / 68, c = i - o * 68;
        W[i] = (c < 64) ? W4[o * 64 + c] : 0.0f;
    }
    __syncthreads();
    int p0 = blockIdx.x * 64;
    for (int i = tid; i < 4096; i += 128) {
        int c = i & 63;
        Y[i] = fmaxf(fmaf(g_y3[p0 * 64 + i], sc[c], sh[c]), 0.0f);
    }
    __syncthreads();
    int o = tid & 63, h = tid >> 6;
    float acc[32];
    #pragma unroll
    for (int p = 0; p < 32; p++) acc[p] = sb[o];
    const float4* wr = (const float4*)(W + o * 68);
    #pragma unroll
    for (int c4 = 0; c4 < 16; c4++) {
        float4 w = wr[c4];
        #pragma unroll
        for (int p = 0; p < 32; p++) {
            float4 v = *(const float4*)(Y + (h * 32 + p) * 64 + c4 * 4);
            acc[p] = fmaf(w.x, v.x, fmaf(w.y, v.y, fmaf(w.z, v.z, fmaf(w.w, v.w, acc[p]))));
        }
    }
    #pragma unroll
    for (int p = 0; p < 32; p++)
        out[(p0 + h * 32 + p) * 64 + o] = acc[p];
}

// ---------------- launch ----------------
extern "C" void kernel_launch(void* const* d_in, const int* in_sizes, int n_in,
                              void* d_out, int out_size) {
    const float* x   = (const float*)d_in[0];
    const float* W1  = (const float*)d_in[1];
    const float* b1  = (const float*)d_in[2];
    const float* g1  = (const float*)d_in[3];
    const float* be1 = (const float*)d_in[4];
    const float* W2  = (const float*)d_in[5];
    const float* b2  = (const float*)d_in[6];
    const float* W3  = (const float*)d_in[7];
    const float* b3  = (const float*)d_in[8];
    const float* g2  = (const float*)d_in[9];
    const float* be2 = (const float*)d_in[10];
    const float* W4  = (const float*)d_in[11];
    const float* b4  = (const float*)d_in[12];
    float* out = (float*)d_out;

    cudaFuncSetAttribute(mega_kernel, cudaFuncAttributeMaxDynamicSharedMemorySize, 53760);

    init_kernel<<<1, 32>>>();
    mega_kernel<<<296, 256, 53760>>>(x, W1, b1, W2, b2, g1, be1);
    mlp3_kernel<<<256, 128>>>(W3, b3);
    bnfin2_kernel<<<1, 64>>>(g2, be2);
    mlp4_kernel<<<256, 128>>>(W4, b4, out);
}